// round 12
// baseline (speedup 1.0000x reference)
#include <cuda_runtime.h>

// ---------------------------------------------------------------------------
// SSIM fused single-kernel. Tile 32x64 outputs/block, 384 threads, 4 CTAs/SM.
// Channel reduction: SSIM needs only (mu1, mu2, E11+E22, E12) -> blur 4
// channels as TWO packed f32x2 streams: AB=(a,b), QP=(a^2+b^2, a*b).
//   P1: stage interleaved AB plane (float2, zero-padded)         [27.2 KB]
//   loop over 2 vertical chunks (h-rows 0..41 / 32..73):
//     P2: horizontal 11-tap conv -> interleaved H plane [col][row] of
//         float4 = (mu1, mu2, Q, P)                              [22.0 KB]
//     P3: vertical 11-tap conv (element-indexed LDS.128, no alignment
//         residues) + SSIM + accumulate
//   block reduce -> global atomic; last block finalizes mean.
// ---------------------------------------------------------------------------

typedef unsigned long long ull;

#define IMG      512
#define TW       32
#define TH       64
#define HALO     5
#define ROWS     74                // TH + 2*HALO
#define ABROW    46                // AB plane row stride (float2 units)
#define NTHREADS 384
#define NWARPS   12
#define NBLOCKS  (16 * 8 * 64)     // 8192

#define CH_ROWS  42                // h-conv rows per chunk (32 outputs + 10)
#define H2COL    43                // H column stride (ulonglong2 units, odd)
#define ABFLOATS (ROWS * ABROW * 2)          // 6808 floats
#define SMEM_BYTES (ABFLOATS * 4 + 32 * H2COL * 16)   // 27,232 + 22,016 = 49,248

#define SSIM_C1 0.0001f
#define SSIM_C2 0.0009f

// 1-D Gaussian, sigma=1.5, 11 taps, normalized (literals -> FFMA-imm)
static __device__ __forceinline__ float gwk(int k) {
    const float g[11] = { 1.0283735e-03f, 7.5987582e-03f, 3.6000773e-02f,
                          1.0936068e-01f, 2.1300554e-01f, 2.6601174e-01f,
                          2.1300554e-01f, 1.0936068e-01f, 3.6000773e-02f,
                          7.5987582e-03f, 1.0283735e-03f };
    return g[k];   // compile-time k -> immediate
}

// packed tap weights in constant memory -> LDCU/uniform regs (no GPR cost)
__constant__ float2 cW2[6] = {
    { 1.0283735e-03f, 1.0283735e-03f },
    { 7.5987582e-03f, 7.5987582e-03f },
    { 3.6000773e-02f, 3.6000773e-02f },
    { 1.0936068e-01f, 1.0936068e-01f },
    { 2.1300554e-01f, 2.1300554e-01f },
    { 2.6601174e-01f, 2.6601174e-01f },
};
__device__ __forceinline__ ull wpk(int ks) {
    return *reinterpret_cast<const ull*>(&cW2[ks]);
}

// packed f32x2 helpers
__device__ __forceinline__ ull pk2(float lo, float hi) {
    ull d; asm("mov.b64 %0, {%1, %2};" : "=l"(d) : "f"(lo), "f"(hi)); return d;
}
__device__ __forceinline__ void unpk2(ull v, float& lo, float& hi) {
    asm("mov.b64 {%0, %1}, %2;" : "=f"(lo), "=f"(hi) : "l"(v));
}
__device__ __forceinline__ ull mul2(ull a, ull b) {
    ull d; asm("mul.rn.f32x2 %0, %1, %2;" : "=l"(d) : "l"(a), "l"(b)); return d;
}
__device__ __forceinline__ ull fma2(ull a, ull b, ull c) {
    ull d; asm("fma.rn.f32x2 %0, %1, %2, %3;" : "=l"(d) : "l"(a), "l"(b), "l"(c)); return d;
}

static __device__ double   g_acc = 0.0;
static __device__ unsigned g_cnt = 0u;

__global__ __launch_bounds__(NTHREADS, 4)
void ssim_kernel(const float* __restrict__ img1, const float* __restrict__ img2,
                 float* __restrict__ out) {
    extern __shared__ float sm[];
    float2*     sAB = reinterpret_cast<float2*>(sm);            // [74][46]
    ulonglong2* sH  = reinterpret_cast<ulonglong2*>(sm + ABFLOATS); // [32 cols][43 rows]
    __shared__ float red[NWARPS];

    const int t    = threadIdx.x;
    const int lane = t & 31;
    const int wid  = t >> 5;        // 0..11
    const int gx0  = blockIdx.x * TW - HALO;
    const int gy0  = blockIdx.y * TH - HALO;
    const float* base1 = img1 + (size_t)blockIdx.z * (IMG * IMG);
    const float* base2 = img2 + (size_t)blockIdx.z * (IMG * IMG);

    // ---- Phase 1: stage interleaved AB (zero-padded), warp per row ----
    for (int r = wid; r < ROWS; r += NWARPS) {
        const int gy = gy0 + r;
        const bool yok = (unsigned)gy < (unsigned)IMG;
        const float* r1 = base1 + gy * IMG;
        const float* r2 = base2 + gy * IMG;
#pragma unroll
        for (int seg = 0; seg < 2; seg++) {
            const int c = lane + seg * 32;
            if (seg == 1 && lane >= 10) break;
            const int gx = gx0 + c;
            const bool ok = yok && (unsigned)gx < (unsigned)IMG;
            sAB[r * ABROW + c] = make_float2(ok ? r1[gx] : 0.0f,
                                             ok ? r2[gx] : 0.0f);
        }
    }
    __syncthreads();

    float lsum = 0.0f;

#pragma unroll
    for (int chunk = 0; chunk < 2; chunk++) {
        const int rowbase = chunk * 32;      // AB row offset for this chunk

        // ---- Phase 2: horizontal conv -> interleaved H[col][row] ----
        // 336 tasks = 8 col-groups x 42 rows; 4 outputs per task.
        if (t < 8 * CH_ROWS) {
            const int g = t / CH_ROWS;       // 0..7
            const int r = t - g * CH_ROWS;   // 0..41
            const float2* abrow = sAB + (rowbase + r) * ABROW + g * 4;

            ull  mAB[4] = {0ull, 0ull, 0ull, 0ull};
            ull  mQP[4] = {0ull, 0ull, 0ull, 0ull};

            // stream 14 window elements as 7x LDS.128 (2 packed pairs each)
#pragma unroll
            for (int blk = 0; blk < 7; blk++) {
                const ulonglong2 v = *reinterpret_cast<const ulonglong2*>(
                    abrow + 2 * blk);
#pragma unroll
                for (int sub = 0; sub < 2; sub++) {
                    const int e = 2 * blk + sub;      // 0..13, compile-time
                    const ull ab = sub ? v.y : v.x;
                    float a, b;
                    unpk2(ab, a, b);
                    const float q = fmaf(a, a, b * b);    // a^2 + b^2
                    const float p = a * b;
                    const ull qp = pk2(q, p);
#pragma unroll
                    for (int j = 0; j < 4; j++) {
                        const int k = e - j;              // compile-time
                        if (k >= 0 && k < 11) {
                            const int ks = (k < 6) ? k : 10 - k;
                            mAB[j] = fma2(wpk(ks), ab, mAB[j]);
                            mQP[j] = fma2(wpk(ks), qp, mQP[j]);
                        }
                    }
                }
            }
#pragma unroll
            for (int j = 0; j < 4; j++) {
                sH[(g * 4 + j) * H2COL + r] = make_ulonglong2(mAB[j], mQP[j]);
            }
        }
        __syncthreads();

        // ---- Phase 3: vertical conv + SSIM (element-indexed LDS.128) ----
        for (int rr = wid; rr < 32; rr += NWARPS) {
            const ulonglong2* pH = sH + lane * H2COL + rr;

            ulonglong2 v0 = pH[0];
            ull accM = mul2(wpk(0), v0.x);
            ull accQ = mul2(wpk(0), v0.y);
#pragma unroll
            for (int k = 1; k < 11; k++) {
                const int ks = (k < 6) ? k : 10 - k;
                const ulonglong2 v = pH[k];
                accM = fma2(wpk(ks), v.x, accM);
                accQ = fma2(wpk(ks), v.y, accQ);
            }

            float m1, m2, Q, P;
            unpk2(accM, m1, m2);
            unpk2(accQ, Q, P);
            const float m1s  = m1 * m1;
            const float m2s  = m2 * m2;
            const float m12  = m1 * m2;
            const float s12  = P - m12;                 // sigma12
            const float ssum = Q - m1s - m2s;           // sigma1^2 + sigma2^2
            const float num = (2.0f * m12 + SSIM_C1) * (2.0f * s12 + SSIM_C2);
            const float den = (m1s + m2s + SSIM_C1) * (ssum + SSIM_C2);
            lsum += __fdividef(num, den);
        }
        __syncthreads();
    }

    // ---- warp reduce -> block reduce -> one global atomic per block ----
#pragma unroll
    for (int off = 16; off > 0; off >>= 1)
        lsum += __shfl_xor_sync(0xffffffffu, lsum, off);
    if (lane == 0) red[wid] = lsum;
    __syncthreads();
    if (t == 0) {
        float s = 0.0f;
#pragma unroll
        for (int i = 0; i < NWARPS; i++) s += red[i];
        atomicAdd(&g_acc, (double)s);
        __threadfence();
        const unsigned old = atomicAdd(&g_cnt, 1u);
        if (old == NBLOCKS - 1) {
            const ull raw = atomicExch(reinterpret_cast<ull*>(&g_acc), 0ull);
            out[0] = (float)(__longlong_as_double(raw) * (1.0 / 16777216.0));
            g_cnt = 0u;
        }
    }
}

extern "C" void kernel_launch(void* const* d_in, const int* in_sizes, int n_in,
                              void* d_out, int out_size) {
    const float* img1 = (const float*)d_in[0];
    const float* img2 = (const float*)d_in[1];
    float* out = (float*)d_out;

    cudaFuncSetAttribute(ssim_kernel,
                         cudaFuncAttributeMaxDynamicSharedMemorySize, SMEM_BYTES);

    dim3 grid(IMG / TW, IMG / TH, 64);   // 16 x 8 x 64 = 8192 blocks
    ssim_kernel<<<grid, NTHREADS, SMEM_BYTES>>>(img1, img2, out);
}

// round 13
// speedup vs baseline: 1.0840x; 1.0840x over previous
#include <cuda_runtime.h>

// ---------------------------------------------------------------------------
// SSIM fused single-kernel. Tile 32x64 outputs/block, 384 threads, 3 CTAs/SM.
// 4-channel reduction: blur (a,b) and (a^2+b^2, a*b) as packed f32x2 streams.
//   P1: stage interleaved AB plane (float2, zero-padded)        [27.2 KB]
//   P2: horizontal 11-tap conv, packed scatter (8 outputs/task) ->
//       two ull planes Hm=(mu1,mu2), Hq=(Q,P), [col][row] stride 75
//       (LDS.64 pair-index 11*lane mod 16 -> conflict-free)     [2x19.2 KB]
//   P3: vertical 11-tap conv with REGISTER SLIDING WINDOW, pass-split
//       (pass A: Hm, pass B reuses window regs: Hq) + SSIM + reduce
// ---------------------------------------------------------------------------

typedef unsigned long long ull;

#define IMG      512
#define TW       32
#define TH       64
#define HALO     5
#define ROWS     74                // TH + 2*HALO
#define ABROW    46                // AB plane row stride (float2 units)
#define ABFLOATS (ROWS * ABROW * 2)          // 6808 floats = 27,232 B
#define NTHREADS 384
#define NWARPS   12
#define NBLOCKS  (16 * 8 * 64)     // 8192

#define HCOL     75                // H column stride in ull units (11*l mod 16 CF)
#define HPLANE   (32 * HCOL)       // 2400 ull = 19,200 B per plane
#define SMEM_BYTES (ABFLOATS * 4 + 2 * HPLANE * 8)   // 65,632 B

#define SSIM_C1 0.0001f
#define SSIM_C2 0.0009f

// packed tap weights in constant memory (uniform regs, no GPR cost)
__constant__ float2 cW2[6] = {
    { 1.0283735e-03f, 1.0283735e-03f },
    { 7.5987582e-03f, 7.5987582e-03f },
    { 3.6000773e-02f, 3.6000773e-02f },
    { 1.0936068e-01f, 1.0936068e-01f },
    { 2.1300554e-01f, 2.1300554e-01f },
    { 2.6601174e-01f, 2.6601174e-01f },
};
__device__ __forceinline__ ull wpk(int ks) {
    return *reinterpret_cast<const ull*>(&cW2[ks]);
}

// packed f32x2 helpers
__device__ __forceinline__ ull pk2(float lo, float hi) {
    ull d; asm("mov.b64 %0, {%1, %2};" : "=l"(d) : "f"(lo), "f"(hi)); return d;
}
__device__ __forceinline__ void unpk2(ull v, float& lo, float& hi) {
    asm("mov.b64 {%0, %1}, %2;" : "=f"(lo), "=f"(hi) : "l"(v));
}
__device__ __forceinline__ ull fma2(ull a, ull b, ull c) {
    ull d; asm("fma.rn.f32x2 %0, %1, %2, %3;" : "=l"(d) : "l"(a), "l"(b), "l"(c)); return d;
}
__device__ __forceinline__ ull mul2(ull a, ull b) {
    ull d; asm("mul.rn.f32x2 %0, %1, %2;" : "=l"(d) : "l"(a), "l"(b)); return d;
}
// packed symmetric 11-tap conv over window y at offset c (compile-time)
__device__ __forceinline__ ull conv11p(const ull* y, int c) {
    ull a = mul2(wpk(0), y[c + 0]);
    a = fma2(wpk(1), y[c + 1], a);
    a = fma2(wpk(2), y[c + 2], a);
    a = fma2(wpk(3), y[c + 3], a);
    a = fma2(wpk(4), y[c + 4], a);
    a = fma2(wpk(5), y[c + 5], a);
    a = fma2(wpk(4), y[c + 6], a);
    a = fma2(wpk(3), y[c + 7], a);
    a = fma2(wpk(2), y[c + 8], a);
    a = fma2(wpk(1), y[c + 9], a);
    a = fma2(wpk(0), y[c + 10], a);
    return a;
}

static __device__ double   g_acc = 0.0;
static __device__ unsigned g_cnt = 0u;

// P3 group: N outputs from one window; pass A (Hm) then pass B (Hq) reusing regs
template<int N>
__device__ __forceinline__ float p3_group(const ull* __restrict__ sHm,
                                          const ull* __restrict__ sHq,
                                          int base) {
    ull y[N + 10];
#pragma unroll
    for (int i = 0; i < N + 10; i++) y[i] = sHm[base + i];
    ull m[N];
#pragma unroll
    for (int i = 0; i < N; i++) m[i] = conv11p(y, i);
#pragma unroll
    for (int i = 0; i < N + 10; i++) y[i] = sHq[base + i];
    float s = 0.0f;
#pragma unroll
    for (int i = 0; i < N; i++) {
        const ull qp = conv11p(y, i);
        float m1, m2, Q, P;
        unpk2(m[i], m1, m2);
        unpk2(qp, Q, P);
        const float m1s  = m1 * m1;
        const float m2s  = m2 * m2;
        const float m12  = m1 * m2;
        const float s12  = P - m12;            // sigma12
        const float ssum = Q - m1s - m2s;      // sigma1^2 + sigma2^2
        const float num = (2.0f * m12 + SSIM_C1) * (2.0f * s12 + SSIM_C2);
        const float den = (m1s + m2s + SSIM_C1) * (ssum + SSIM_C2);
        s += __fdividef(num, den);
    }
    return s;
}

__global__ __launch_bounds__(NTHREADS, 3)
void ssim_kernel(const float* __restrict__ img1, const float* __restrict__ img2,
                 float* __restrict__ out) {
    extern __shared__ float sm[];
    float2* sAB = reinterpret_cast<float2*>(sm);                 // [74][46]
    ull*    sHm = reinterpret_cast<ull*>(sm + ABFLOATS);         // [32][75]
    ull*    sHq = sHm + HPLANE;                                  // [32][75]
    __shared__ float red[NWARPS];

    const int t    = threadIdx.x;
    const int lane = t & 31;
    const int wid  = t >> 5;        // 0..11
    const int gx0  = blockIdx.x * TW - HALO;
    const int gy0  = blockIdx.y * TH - HALO;
    const float* base1 = img1 + (size_t)blockIdx.z * (IMG * IMG);
    const float* base2 = img2 + (size_t)blockIdx.z * (IMG * IMG);

    // ---- Phase 1: stage interleaved AB (zero-padded), warp per row ----
    for (int r = wid; r < ROWS; r += NWARPS) {
        const int gy = gy0 + r;
        const bool yok = (unsigned)gy < (unsigned)IMG;
        const float* r1 = base1 + gy * IMG;
        const float* r2 = base2 + gy * IMG;
#pragma unroll
        for (int seg = 0; seg < 2; seg++) {
            const int c = lane + seg * 32;
            if (seg == 1 && lane >= 10) break;
            const int gx = gx0 + c;
            const bool ok = yok && (unsigned)gx < (unsigned)IMG;
            sAB[r * ABROW + c] = make_float2(ok ? r1[gx] : 0.0f,
                                             ok ? r2[gx] : 0.0f);
        }
    }
    __syncthreads();

    // ---- Phase 2: horizontal conv, packed scatter, 8 outputs per task ----
    // 296 tasks = 4 col-groups x 74 rows.
    if (t < 4 * ROWS) {
        const int g = t / ROWS;          // 0..3
        const int r = t - g * ROWS;      // 0..73
        const float2* abrow = sAB + r * ABROW + g * 8;

        ull mAB[8] = {0,0,0,0,0,0,0,0};
        ull mQP[8] = {0,0,0,0,0,0,0,0};

        // stream 18 window elements as 9x LDS.128 (2 packed pairs each)
#pragma unroll
        for (int blk = 0; blk < 9; blk++) {
            const ulonglong2 v = *reinterpret_cast<const ulonglong2*>(
                abrow + 2 * blk);
#pragma unroll
            for (int sub = 0; sub < 2; sub++) {
                const int e = 2 * blk + sub;      // 0..17, compile-time
                const ull ab = sub ? v.y : v.x;
                float a, b;
                unpk2(ab, a, b);
                const float q = fmaf(a, a, b * b);    // a^2 + b^2
                const float p = a * b;
                const ull qp = pk2(q, p);
#pragma unroll
                for (int j = 0; j < 8; j++) {
                    const int k = e - j;              // compile-time
                    if (k >= 0 && k < 11) {
                        const int ks = (k < 6) ? k : 10 - k;
                        mAB[j] = fma2(wpk(ks), ab, mAB[j]);
                        mQP[j] = fma2(wpk(ks), qp, mQP[j]);
                    }
                }
            }
        }
        // ST.64 into transposed H planes (phase banks: r mod 16, conflict-free)
#pragma unroll
        for (int j = 0; j < 8; j++) {
            const int c = g * 8 + j;
            sHm[c * HCOL + r] = mAB[j];
            sHq[c * HCOL + r] = mQP[j];
        }
    }
    __syncthreads();

    // ---- Phase 3: vertical conv, register sliding window, pass-split ----
    float lsum = 0.0f;
    {
        const int col = lane;
        if (wid < 8) {                    // 6 rows: two groups of 3
            const int r0 = 6 * wid;
            const int base = col * HCOL + r0;
            lsum += p3_group<3>(sHm, sHq, base);
            lsum += p3_group<3>(sHm, sHq, base + 3);
        } else {                          // 4 rows: two groups of 2
            const int r0 = 48 + 4 * (wid - 8);
            const int base = col * HCOL + r0;
            lsum += p3_group<2>(sHm, sHq, base);
            lsum += p3_group<2>(sHm, sHq, base + 2);
        }
    }

    // ---- warp reduce -> block reduce -> one global atomic per block ----
#pragma unroll
    for (int off = 16; off > 0; off >>= 1)
        lsum += __shfl_xor_sync(0xffffffffu, lsum, off);
    if (lane == 0) red[wid] = lsum;
    __syncthreads();
    if (t == 0) {
        float s = 0.0f;
#pragma unroll
        for (int i = 0; i < NWARPS; i++) s += red[i];
        atomicAdd(&g_acc, (double)s);
        __threadfence();
        const unsigned old = atomicAdd(&g_cnt, 1u);
        if (old == NBLOCKS - 1) {
            const ull raw = atomicExch(reinterpret_cast<ull*>(&g_acc), 0ull);
            out[0] = (float)(__longlong_as_double(raw) * (1.0 / 16777216.0));
            g_cnt = 0u;
        }
    }
}

extern "C" void kernel_launch(void* const* d_in, const int* in_sizes, int n_in,
                              void* d_out, int out_size) {
    const float* img1 = (const float*)d_in[0];
    const float* img2 = (const float*)d_in[1];
    float* out = (float*)d_out;

    cudaFuncSetAttribute(ssim_kernel,
                         cudaFuncAttributeMaxDynamicSharedMemorySize, SMEM_BYTES);

    dim3 grid(IMG / TW, IMG / TH, 64);   // 16 x 8 x 64 = 8192 blocks
    ssim_kernel<<<grid, NTHREADS, SMEM_BYTES>>>(img1, img2, out);
}